// round 14
// baseline (speedup 1.0000x reference)
#include <cuda_runtime.h>
#include <cuda_bf16.h>
#include <math.h>

#define B_   2
#define T_   4
#define HH   256
#define WW   256
#define SP_  64
#define NH   7
#define NN   49
#define CE   512
#define DD   128
#define TEMP_ 0.07f

// ---------------- scratch ----------------
__device__ float g_ws   [B_*T_*NN*SP_];
__device__ float g_qpart[4][B_*T_*NN*DD];
__device__ float g_qsp  [B_*T_*SP_*DD];
__device__ float g_E    [6*SP_*SP_];
__device__ unsigned g_barcnt[2];   // monotonic, replay-safe

// ---------------- 1. fused: ws histograms + proj K-split (proven R10 version) ----------------
__global__ void fused_in_kernel(const int* __restrict__ sp_mask,
                                const float* __restrict__ feats,
                                const float* __restrict__ Wh,
                                float* __restrict__ out, int write_loss) {
    int bx = blockIdx.x;
    int tid = threadIdx.x;
    if (bx == 0 && tid == 0 && write_loss) out[0] = 0.f;
    if (bx < 392) {
        int w  = bx % NN;
        int bt = bx / NN;
        int wy = w / NH, wx = w % NH;
        int y0 = wy * 32, x0 = wx * 32;
        __shared__ float hist[2][SP_];
        if (tid < 2 * SP_) hist[tid >> 6][tid & 63] = 0.f;
        __syncthreads();
        int par = (tid >> 5) & 1;
        const int* base = sp_mask + bt * (HH * WW);
        #pragma unroll
        for (int k = 0; k < 4; k++) {
            int idx = (tid + k * 256) * 4;
            int py = idx >> 6, px = idx & 63;
            int y = y0 + py;
            float cy = (y >= 32 && y < 224) ? 0.5f : 1.0f;
            int4 s4 = *(const int4*)(base + y * WW + x0 + px);
            int xb = x0 + px;
            float cx0 = (xb     >= 32 && xb     < 224) ? 0.5f : 1.0f;
            float cx1 = (xb + 1 >= 32 && xb + 1 < 224) ? 0.5f : 1.0f;
            float cx2 = (xb + 2 >= 32 && xb + 2 < 224) ? 0.5f : 1.0f;
            float cx3 = (xb + 3 >= 32 && xb + 3 < 224) ? 0.5f : 1.0f;
            atomicAdd(&hist[par][s4.x], cy * cx0);
            atomicAdd(&hist[par][s4.y], cy * cx1);
            atomicAdd(&hist[par][s4.z], cy * cx2);
            atomicAdd(&hist[par][s4.w], cy * cx3);
        }
        __syncthreads();
        if (tid < SP_) g_ws[(bt * NN + w) * SP_ + tid] = hist[0][tid] + hist[1][tid];
    } else {
        int pid = bx - 392;
        int n   = pid % NN;
        int kq  = pid / NN;
        __shared__ float sf[2][128][4];
        __shared__ float partr[2][8][DD];
        {
            int bb = tid >> 7, row = tid & 127;
            const float4* src = (const float4*)feats + ((size_t)(bb * NN + n) * CE + kq * 128 + row);
            *(float4*)&sf[bb][row][0] = *src;
        }
        __syncthreads();
        int ch = tid >> 7, d = tid & 127;
        float acc[2][4] = {};
        const float* wp = Wh + (size_t)(kq * 128 + ch * 64) * DD + d;
        #pragma unroll
        for (int cc = 0; cc < 2; cc++) {
            float wv[32];
            #pragma unroll
            for (int u = 0; u < 32; u++)
                wv[u] = wp[(size_t)(cc * 32 + u) * DD];
            #pragma unroll
            for (int u = 0; u < 32; u++) {
                int cl = cc * 32 + u;
                float4 f0 = *(const float4*)&sf[0][ch * 64 + cl][0];
                float4 f1 = *(const float4*)&sf[1][ch * 64 + cl][0];
                acc[0][0] = fmaf(f0.x, wv[u], acc[0][0]);
                acc[0][1] = fmaf(f0.y, wv[u], acc[0][1]);
                acc[0][2] = fmaf(f0.z, wv[u], acc[0][2]);
                acc[0][3] = fmaf(f0.w, wv[u], acc[0][3]);
                acc[1][0] = fmaf(f1.x, wv[u], acc[1][0]);
                acc[1][1] = fmaf(f1.y, wv[u], acc[1][1]);
                acc[1][2] = fmaf(f1.z, wv[u], acc[1][2]);
                acc[1][3] = fmaf(f1.w, wv[u], acc[1][3]);
            }
        }
        #pragma unroll
        for (int b = 0; b < 2; b++)
            #pragma unroll
            for (int t = 0; t < 4; t++)
                partr[ch][b * 4 + t][d] = acc[b][t];
        __syncthreads();
        if (ch == 0) {
            #pragma unroll
            for (int r = 0; r < 8; r++)
                g_qpart[kq][((size_t)r * NN + n) * DD + d] = partr[0][r][d] + partr[1][r][d];
        }
    }
}

// ---------------- grid barrier ----------------
#define NBLK 64
__device__ __forceinline__ void gridbar(int slot) {
    __syncthreads();
    __threadfence();
    if (threadIdx.x == 0) {
        unsigned my = atomicAdd(&g_barcnt[slot], 1u) + 1u;
        unsigned target = ((my + NBLK - 1u) / NBLK) * NBLK;
        while (*(volatile unsigned*)&g_barcnt[slot] < target) { }
    }
    __syncthreads();
    __threadfence();
}

// ---------------- 2. mega tail ----------------
#define ESTRIDE 65
#define BSTRIDE 68
// chain: 3*4160 + 2*4*68 + 384 + 4 = 13412; qsp 9784; as1 9344
#define SMEM_MEGA (13440 * 4)

__device__ __forceinline__ void mm4v(const float* __restrict__ In,
                                     const float* __restrict__ E,
                                     bool colAcc,
                                     const float* __restrict__ outScale,
                                     float* __restrict__ Out) {
    int tid = threadIdx.x;
    int r = tid >> 6, m = tid & 63;
    const float* ap = In + r * BSTRIDE;
    float acc0 = 0.f, acc1 = 0.f;
    if (colAcc) {
        const float* ep = E + m * ESTRIDE;
        #pragma unroll
        for (int k = 0; k < 32; k++) {
            acc0 = fmaf(ap[k],      ep[k],      acc0);
            acc1 = fmaf(ap[k + 32], ep[k + 32], acc1);
        }
    } else {
        #pragma unroll
        for (int k = 0; k < 32; k++) {
            acc0 = fmaf(ap[k],      E[k * ESTRIDE + m],        acc0);
            acc1 = fmaf(ap[k + 32], E[(k + 32) * ESTRIDE + m], acc1);
        }
    }
    float sc = outScale ? outScale[m] : 1.0f;
    __syncthreads();
    Out[r * BSTRIDE + m] = (acc0 + acc1) * sc;
    __syncthreads();
}

__global__ void mega_kernel(float* __restrict__ out, int aa_base, int write_loss) {
    extern __shared__ float sm[];
    int bx  = blockIdx.x;     // 0..63
    int tid = threadIdx.x;

    // ======== phase 1: qsp (ALL 64 blocks: bt x d-quarter x s-half) ========
    {
        int bt = bx >> 3;
        int dq = (bx >> 1) & 3;
        int sh = bx & 1;
        float (*sq)[DD]  = (float(*)[DD]) sm;                 // 6272
        float (*sw)[SP_] = (float(*)[SP_])(sm + 6272);        // 3136
        float* sinv  = sm + 9408;                             // 49 (+pad)
        float* sden  = sm + 9464;                             // 64
        float* sdenP = sm + 9528;                             // 256
        {
            const float4* p0 = (const float4*)(g_qpart[0] + (size_t)bt * NN * DD);
            const float4* p1 = (const float4*)(g_qpart[1] + (size_t)bt * NN * DD);
            const float4* p2 = (const float4*)(g_qpart[2] + (size_t)bt * NN * DD);
            const float4* p3 = (const float4*)(g_qpart[3] + (size_t)bt * NN * DD);
            float* sqf = sm;
            for (int i = tid; i < 1568; i += 256) {
                float4 a = p0[i], b = p1[i], c = p2[i], d = p3[i];
                float4 r;
                r.x = a.x + b.x + c.x + d.x;
                r.y = a.y + b.y + c.y + d.y;
                r.z = a.z + b.z + c.z + d.z;
                r.w = a.w + b.w + c.w + d.w;
                *(float4*)(sqf + i * 4) = r;
            }
            const float4* pw = (const float4*)(g_ws + (size_t)bt * NN * SP_);
            float* swf = sm + 6272;
            for (int i = tid; i < 784; i += 256)
                *(float4*)(swf + i * 4) = pw[i];
        }
        __syncthreads();
        int wid = tid >> 5, lane = tid & 31;
        for (int n = wid; n < NN; n += 8) {
            float v0 = sq[n][lane], v1 = sq[n][lane + 32],
                  v2 = sq[n][lane + 64], v3 = sq[n][lane + 96];
            float ss = v0 * v0 + v1 * v1 + v2 * v2 + v3 * v3;
            #pragma unroll
            for (int o = 16; o > 0; o >>= 1) ss += __shfl_xor_sync(0xffffffffu, ss, o);
            if (lane == 0) sinv[n] = 1.0f / fmaxf(sqrtf(ss), 1e-12f);
        }
        {
            int grp = tid >> 6, s = tid & 63;
            float p = 0.f;
            for (int n = grp; n < NN; n += 4) p += sw[n][s];
            sdenP[grp * 64 + s] = p;
        }
        __syncthreads();
        if (tid < SP_)
            sden[tid] = 1.0f / (sdenP[tid] + sdenP[64 + tid]
                              + sdenP[128 + tid] + sdenP[192 + tid] + 1e-20f);
        __syncthreads();
        // scale only our s-half
        for (int i = tid; i < NN * 32; i += 256) {
            int n = i >> 5, s = sh * 32 + (i & 31);
            sw[n][s] *= sinv[n] * sden[s];
        }
        __syncthreads();
        int d     = dq * 32 + (tid & 31);
        int sbase = sh * 32 + (tid >> 5) * 4;
        float acc[4] = {};
        for (int n = 0; n < NN; n++) {
            float qv = sq[n][d];
            float4 w = *(const float4*)&sw[n][sbase];
            acc[0] = fmaf(w.x, qv, acc[0]);
            acc[1] = fmaf(w.y, qv, acc[1]);
            acc[2] = fmaf(w.z, qv, acc[2]);
            acc[3] = fmaf(w.w, qv, acc[3]);
        }
        #pragma unroll
        for (int i = 0; i < 4; i++)
            g_qsp[((size_t)bt * SP_ + sbase + i) * DD + d] = acc[i];
    }

    gridbar(0);

    // ======== phase 2: as1 (blocks 0..47) -> g_E only ========
    if (bx < 48) {
        int job = bx >> 3;
        int rb  = bx & 7;
        int r0  = rb * 8;
        int b = job / 3, t = job % 3;
        const float* X = g_qsp + (size_t)(b * T_ + t)     * SP_ * DD;
        const float* Y = g_qsp + (size_t)(b * T_ + t + 1) * SP_ * DD;
        float (*sYt)[65] = (float(*)[65])sm;                  // 8320
        float (*sXr)[DD] = (float(*)[DD])(sm + 8320);         // 1024
        {
            const float4* Y4 = (const float4*)Y;
            for (int i = tid; i < 2048; i += 256) {
                int m = i >> 5, k4 = i & 31;
                float4 v = __ldcg(Y4 + i);
                sYt[k4 * 4 + 0][m] = v.x;
                sYt[k4 * 4 + 1][m] = v.y;
                sYt[k4 * 4 + 2][m] = v.z;
                sYt[k4 * 4 + 3][m] = v.w;
            }
            const float4* X4 = (const float4*)(X + (size_t)r0 * DD);
            int r = tid >> 5, k4 = tid & 31;
            float4 v = __ldcg(X4 + r * 32 + k4);
            *(float4*)&sXr[r][k4 * 4] = v;
        }
        __syncthreads();
        int m  = tid & 63;
        int lr = (tid >> 6) * 2;
        float a0 = 0.f, a1 = 0.f;
        #pragma unroll 8
        for (int k = 0; k < DD; k++) {
            float yv = sYt[k][m];
            a0 = fmaf(sXr[lr][k],     yv, a0);
            a1 = fmaf(sXr[lr + 1][k], yv, a1);
        }
        float e0 = expf(a0 * (1.0f / TEMP_)) - 1.0f;
        float e1 = expf(a1 * (1.0f / TEMP_)) - 1.0f;
        e0 *= e0; e1 *= e1;
        g_E[(size_t)job * 4096 + (r0 + lr) * 64 + m]     = e0;
        g_E[(size_t)job * 4096 + (r0 + lr + 1) * 64 + m] = e1;
    }

    gridbar(1);

    // ======== phase 3: chain (all 64 blocks; kind = aa1 | aa2) ========
    {
        float* buf0  = sm + 3 * 64 * ESTRIDE;
        float* buf1  = buf0 + 4 * BSTRIDE;
        float* sinvC = buf1 + 4 * BSTRIDE;   // [384]
        float* slloss = sinvC + 384;         // [4]
        int kind = bx >> 5;                 // 0: aa1, 1: aa2
        int b    = (bx >> 4) & 1;
        int r0   = (bx & 15) * 4;
        int j0   = b * 3;
        int nmats = kind ? 3 : 2;

        // load raw E matrices into smem (stride 65)
        for (int mat = 0; mat < nmats; mat++) {
            const float4* Eg = (const float4*)(g_E + (size_t)(j0 + mat) * 4096);
            float* Es = sm + mat * 64 * ESTRIDE;
            for (int i = tid; i < 1024; i += 256) {
                int n = i >> 4, mb = (i & 15) * 4;
                float4 v = __ldcg(Eg + i);
                Es[n * ESTRIDE + mb + 0] = v.x;
                Es[n * ESTRIDE + mb + 1] = v.y;
                Es[n * ESTRIDE + mb + 2] = v.z;
                Es[n * ESTRIDE + mb + 3] = v.w;
            }
        }
        __syncthreads();
        // row/col sums from smem (replaces g_rs/g_csp round trips)
        for (int idx = tid; idx < nmats * 64; idx += 256) {
            int j = idx >> 6, n = idx & 63;
            const float* Es = sm + j * 64 * ESTRIDE;
            float s = 0.f;
            #pragma unroll 8
            for (int m = 0; m < 64; m++) s += Es[n * ESTRIDE + m];
            sinvC[j * 64 + n] = 1.0f / (s + 1e-5f);
        }
        for (int idx = tid; idx < nmats * 64; idx += 256) {
            int j = idx >> 6, m = idx & 63;
            const float* Es = sm + j * 64 * ESTRIDE;
            float s = 0.f;
            #pragma unroll 8
            for (int n = 0; n < 64; n++) s += Es[n * ESTRIDE + m];
            sinvC[192 + j * 64 + m] = 1.0f / (s + 1e-5f);
        }
        __syncthreads();
        float* E0s = sm;
        float* E1s = sm + 1 * 64 * ESTRIDE;
        float* E2s = sm + 2 * 64 * ESTRIDE;
        {
            int r = tid >> 6, m = tid & 63;
            buf0[r * BSTRIDE + m] = E0s[(r0 + r) * ESTRIDE + m]
                                    * sinvC[r0 + r] * sinvC[64 + m];
        }
        __syncthreads();

        float* res;
        if (kind == 0) {
            mm4v(buf0, E1s, false, sinvC + 256, buf1);  // P      -> *cinv1
            mm4v(buf1, E1s, true,  sinvC + 192, buf0);  // @A21_1 -> *cinv0
            mm4v(buf0, E0s, true,  nullptr,     buf1);  // @A21_0 = aa1
            res = buf1;
        } else {
            mm4v(buf0, E1s, false, sinvC + 128, buf1);  // P      -> *rinv2
            mm4v(buf1, E2s, false, sinvC + 320, buf0);  // @A12_2 -> *cinv2
            mm4v(buf0, E2s, true,  sinvC + 256, buf1);  // @A21_2 -> *cinv1
            mm4v(buf1, E1s, true,  sinvC + 192, buf0);  // @A21_1 -> *cinv0
            mm4v(buf0, E0s, true,  nullptr,     buf1);  // @A21_0 = aa2
            res = buf1;
        }

        {
            int r = tid >> 6, m = tid & 63;
            float* dst = out + aa_base + (size_t)(kind * B_ + b) * 4096;
            dst[(r0 + r) * 64 + m] = res[r * BSTRIDE + m];
            if (write_loss && tid < 4) {
                float s = 0.f;
                #pragma unroll 8
                for (int j = 0; j < 64; j++) s += res[tid * BSTRIDE + j];
                float diag = res[tid * BSTRIDE + (r0 + tid)] + 1e-20f;
                slloss[tid] = logf(s + 6.4e-19f) - logf(diag);
            }
            __syncthreads();
            if (write_loss && tid == 0) {
                float s = slloss[0] + slloss[1] + slloss[2] + slloss[3];
                atomicAdd(out, s * (1.0f / 128.0f));
            }
        }
    }
}

// ---------------- launch ----------------
extern "C" void kernel_launch(void* const* d_in, const int* in_sizes, int n_in,
                              void* d_out, int out_size) {
    const float* feats   = (const float*)d_in[0];
    const float* W_head  = (const float*)d_in[1];
    const int*   sp_mask = (const int*)  d_in[2];
    float* out = (float*)d_out;

    int aa_base    = (out_size > 2 * B_ * SP_ * SP_) ? 1 : 0;
    int write_loss = aa_base;

    cudaFuncSetAttribute(mega_kernel, cudaFuncAttributeMaxDynamicSharedMemorySize, SMEM_MEGA);

    fused_in_kernel<<<588, 256>>>(sp_mask, feats, W_head, out, write_loss);
    mega_kernel    <<<NBLK, 256, SMEM_MEGA>>>(out, aa_base, write_loss);
}

// round 16
// speedup vs baseline: 1.4472x; 1.4472x over previous
#include <cuda_runtime.h>
#include <cuda_bf16.h>
#include <math.h>

#define B_   2
#define T_   4
#define HH   256
#define WW   256
#define SP_  64
#define NH   7
#define NN   49
#define CE   512
#define DD   128
#define TEMP_ 0.07f

// ---------------- scratch ----------------
__device__ float g_ws   [B_*T_*NN*SP_];
__device__ float g_qpart[4][B_*T_*NN*DD];
__device__ float g_qsp  [B_*T_*SP_*DD];
__device__ float g_E    [6*SP_*SP_];
__device__ float g_rs   [6*SP_];
__device__ float g_csp  [6*8*SP_];
__device__ unsigned g_barcnt[2];   // monotonic, replay-safe

// ---------------- 1. fused: ws histograms + proj K-split ----------------
__global__ void fused_in_kernel(const int* __restrict__ sp_mask,
                                const float* __restrict__ feats,
                                const float* __restrict__ Wh,
                                float* __restrict__ out, int write_loss) {
    int bx = blockIdx.x;
    int tid = threadIdx.x;
    if (bx == 0 && tid == 0 && write_loss) out[0] = 0.f;
    if (bx < 392) {
        int w  = bx % NN;
        int bt = bx / NN;
        int wy = w / NH, wx = w % NH;
        int y0 = wy * 32, x0 = wx * 32;
        __shared__ float hist[2][SP_];
        if (tid < 2 * SP_) hist[tid >> 6][tid & 63] = 0.f;
        __syncthreads();
        int par = (tid >> 5) & 1;
        const int* base = sp_mask + bt * (HH * WW);
        #pragma unroll
        for (int k = 0; k < 4; k++) {
            int idx = (tid + k * 256) * 4;       // 4 consecutive pixels
            int py = idx >> 6, px = idx & 63;
            int y = y0 + py;
            float cy = (y >= 32 && y < 224) ? 0.5f : 1.0f;
            int4 s4 = *(const int4*)(base + y * WW + x0 + px);
            int xb = x0 + px;
            float cx0 = (xb     >= 32 && xb     < 224) ? 0.5f : 1.0f;
            float cx1 = (xb + 1 >= 32 && xb + 1 < 224) ? 0.5f : 1.0f;
            float cx2 = (xb + 2 >= 32 && xb + 2 < 224) ? 0.5f : 1.0f;
            float cx3 = (xb + 3 >= 32 && xb + 3 < 224) ? 0.5f : 1.0f;
            atomicAdd(&hist[par][s4.x], cy * cx0);
            atomicAdd(&hist[par][s4.y], cy * cx1);
            atomicAdd(&hist[par][s4.z], cy * cx2);
            atomicAdd(&hist[par][s4.w], cy * cx3);
        }
        __syncthreads();
        if (tid < SP_) g_ws[(bt * NN + w) * SP_ + tid] = hist[0][tid] + hist[1][tid];
    } else {
        int pid = bx - 392;
        int n   = pid % NN;
        int kq  = pid / NN;
        __shared__ float sf[2][128][4];
        __shared__ float partr[2][8][DD];
        int ch = tid >> 7, d = tid & 127;
        const float* wp = Wh + (size_t)(kq * 128 + ch * 64) * DD + d;
        {
            int bb = tid >> 7, row = tid & 127;
            const float4* src = (const float4*)feats + ((size_t)(bb * NN + n) * CE + kq * 128 + row);
            *(float4*)&sf[bb][row][0] = *src;
        }
        // prefetch first W batch BEFORE the sync (overlaps sf latency)
        float wv[32];
        #pragma unroll
        for (int u = 0; u < 32; u++)
            wv[u] = wp[(size_t)u * DD];
        __syncthreads();
        float acc[2][4] = {};
        #pragma unroll
        for (int cc = 0; cc < 2; cc++) {
            if (cc == 1) {
                #pragma unroll
                for (int u = 0; u < 32; u++)
                    wv[u] = wp[(size_t)(32 + u) * DD];
            }
            #pragma unroll
            for (int u = 0; u < 32; u++) {
                int cl = cc * 32 + u;
                float4 f0 = *(const float4*)&sf[0][ch * 64 + cl][0];
                float4 f1 = *(const float4*)&sf[1][ch * 64 + cl][0];
                acc[0][0] = fmaf(f0.x, wv[u], acc[0][0]);
                acc[0][1] = fmaf(f0.y, wv[u], acc[0][1]);
                acc[0][2] = fmaf(f0.z, wv[u], acc[0][2]);
                acc[0][3] = fmaf(f0.w, wv[u], acc[0][3]);
                acc[1][0] = fmaf(f1.x, wv[u], acc[1][0]);
                acc[1][1] = fmaf(f1.y, wv[u], acc[1][1]);
                acc[1][2] = fmaf(f1.z, wv[u], acc[1][2]);
                acc[1][3] = fmaf(f1.w, wv[u], acc[1][3]);
            }
        }
        #pragma unroll
        for (int b = 0; b < 2; b++)
            #pragma unroll
            for (int t = 0; t < 4; t++)
                partr[ch][b * 4 + t][d] = acc[b][t];
        __syncthreads();
        if (ch == 0) {
            #pragma unroll
            for (int r = 0; r < 8; r++)
                g_qpart[kq][((size_t)r * NN + n) * DD + d] = partr[0][r][d] + partr[1][r][d];
        }
    }
}

// ---------------- grid barrier ----------------
#define NBLK 64
__device__ __forceinline__ void gridbar(int slot) {
    __syncthreads();
    __threadfence();
    if (threadIdx.x == 0) {
        unsigned my = atomicAdd(&g_barcnt[slot], 1u) + 1u;
        unsigned target = ((my + NBLK - 1u) / NBLK) * NBLK;
        while (*(volatile unsigned*)&g_barcnt[slot] < target) { }
    }
    __syncthreads();
    __threadfence();
}

// ---------------- 2. mega tail ----------------
#define ESTRIDE 65
#define BSTRIDE 68
// chain: 3*64*65 + 2*4*68 + 384 + 4 = 13412; qsp 9524; as1 9864
#define SMEM_MEGA (13440 * 4)

__device__ __forceinline__ void mm4v(const float* __restrict__ In,
                                     const float* __restrict__ E,
                                     bool colAcc,
                                     const float* __restrict__ outScale,
                                     float* __restrict__ Out) {
    int tid = threadIdx.x;
    int r = tid >> 6, m = tid & 63;
    const float* ap = In + r * BSTRIDE;
    float acc0 = 0.f, acc1 = 0.f;
    if (colAcc) {
        const float* ep = E + m * ESTRIDE;
        #pragma unroll
        for (int k = 0; k < 32; k++) {
            acc0 = fmaf(ap[k],      ep[k],      acc0);
            acc1 = fmaf(ap[k + 32], ep[k + 32], acc1);
        }
    } else {
        #pragma unroll
        for (int k = 0; k < 32; k++) {
            acc0 = fmaf(ap[k],      E[k * ESTRIDE + m],        acc0);
            acc1 = fmaf(ap[k + 32], E[(k + 32) * ESTRIDE + m], acc1);
        }
    }
    float sc = outScale ? outScale[m] : 1.0f;
    __syncthreads();
    Out[r * BSTRIDE + m] = (acc0 + acc1) * sc;
    __syncthreads();
}

__global__ void mega_kernel(float* __restrict__ out, int aa_base, int write_loss) {
    extern __shared__ float sm[];
    int bx  = blockIdx.x;     // 0..63
    int tid = threadIdx.x;

    // ======== phase 1: qsp (blocks 0..31) ========
    if (bx < 32) {
        int bt = bx >> 2;
        int dq = bx & 3;
        float (*sq)[DD]  = (float(*)[DD]) sm;
        float (*sw)[SP_] = (float(*)[SP_])(sm + 6272);
        float* sinv = sm + 9408;
        float* sden = sm + 9460;
        {
            const float4* p0 = (const float4*)(g_qpart[0] + (size_t)bt * NN * DD);
            const float4* p1 = (const float4*)(g_qpart[1] + (size_t)bt * NN * DD);
            const float4* p2 = (const float4*)(g_qpart[2] + (size_t)bt * NN * DD);
            const float4* p3 = (const float4*)(g_qpart[3] + (size_t)bt * NN * DD);
            float* sqf = sm;
            for (int i = tid; i < 1568; i += 256) {
                float4 a = p0[i], b = p1[i], c = p2[i], d = p3[i];
                float4 r;
                r.x = a.x + b.x + c.x + d.x;
                r.y = a.y + b.y + c.y + d.y;
                r.z = a.z + b.z + c.z + d.z;
                r.w = a.w + b.w + c.w + d.w;
                *(float4*)(sqf + i * 4) = r;
            }
            const float4* pw = (const float4*)(g_ws + (size_t)bt * NN * SP_);
            float* swf = sm + 6272;
            for (int i = tid; i < 784; i += 256)
                *(float4*)(swf + i * 4) = pw[i];
        }
        __syncthreads();
        // norms: thread-per-(n, quarter), rotation-indexed (conflict-free), 2-shfl reduce
        if (tid < NN * 4) {
            int n = tid >> 2, q = tid & 3;
            int rot = tid & 31;
            float ss = 0.f;
            #pragma unroll
            for (int j = 0; j < 32; j++) {
                float v = sq[n][q * 32 + ((j + rot) & 31)];
                ss = fmaf(v, v, ss);
            }
            unsigned grpmask = 0xFu << ((tid & 31) & ~3);
            ss += __shfl_xor_sync(grpmask, ss, 1);
            ss += __shfl_xor_sync(grpmask, ss, 2);
            if (q == 0) sinv[n] = 1.0f / fmaxf(sqrtf(ss), 1e-12f);
        }
        if (tid < SP_) {
            float s = 0.f;
            for (int n = 0; n < NN; n++) s += sw[n][tid];
            sden[tid] = 1.0f / (s + 1e-20f);
        }
        __syncthreads();
        for (int i = tid; i < NN * SP_; i += 256) {
            int n = i >> 6, s = i & 63;
            sw[n][s] *= sinv[n] * sden[s];
        }
        __syncthreads();
        int d  = tid & 31;
        int dd = dq * 32 + d;
        int sg = tid >> 5;
        float acc[8] = {};
        for (int n = 0; n < NN; n++) {
            float qv = sq[n][dd];
            #pragma unroll
            for (int i = 0; i < 8; i++)
                acc[i] = fmaf(sw[n][sg * 8 + i], qv, acc[i]);
        }
        #pragma unroll
        for (int i = 0; i < 8; i++)
            g_qsp[((size_t)bt * SP_ + sg * 8 + i) * DD + dd] = acc[i];
    }

    gridbar(0);

    // ======== phase 2: as1 (blocks 0..47) ========
    if (bx < 48) {
        int job = bx >> 3;
        int rb  = bx & 7;
        int r0  = rb * 8;
        int b = job / 3, t = job % 3;
        const float* X = g_qsp + (size_t)(b * T_ + t)     * SP_ * DD;
        const float* Y = g_qsp + (size_t)(b * T_ + t + 1) * SP_ * DD;
        float (*sYt)[65] = (float(*)[65])sm;
        float (*sXr)[DD] = (float(*)[DD])(sm + 8320);
        float (*sE)[65]  = (float(*)[65])(sm + 9344);
        {
            const float4* Y4 = (const float4*)Y;
            for (int i = tid; i < 2048; i += 256) {
                int m = i >> 5, k4 = i & 31;
                float4 v = __ldcg(Y4 + i);
                sYt[k4 * 4 + 0][m] = v.x;
                sYt[k4 * 4 + 1][m] = v.y;
                sYt[k4 * 4 + 2][m] = v.z;
                sYt[k4 * 4 + 3][m] = v.w;
            }
            const float4* X4 = (const float4*)(X + (size_t)r0 * DD);
            int r = tid >> 5, k4 = tid & 31;
            float4 v = __ldcg(X4 + r * 32 + k4);
            *(float4*)&sXr[r][k4 * 4] = v;
        }
        __syncthreads();
        int m  = tid & 63;
        int lr = (tid >> 6) * 2;
        float a0 = 0.f, a1 = 0.f;
        #pragma unroll 8
        for (int k = 0; k < DD; k++) {
            float yv = sYt[k][m];
            a0 = fmaf(sXr[lr][k],     yv, a0);
            a1 = fmaf(sXr[lr + 1][k], yv, a1);
        }
        float e0 = expf(a0 * (1.0f / TEMP_)) - 1.0f;
        float e1 = expf(a1 * (1.0f / TEMP_)) - 1.0f;
        e0 *= e0; e1 *= e1;
        sE[lr][m] = e0; sE[lr + 1][m] = e1;
        g_E[(size_t)job * 4096 + (r0 + lr) * 64 + m]     = e0;
        g_E[(size_t)job * 4096 + (r0 + lr + 1) * 64 + m] = e1;
        __syncthreads();
        if (tid < 8) {
            float s = 0.f;
            for (int j = 0; j < 64; j++) s += sE[tid][j];
            g_rs[job * 64 + r0 + tid] = s;
        } else if (tid >= 64 && tid < 128) {
            int c = tid - 64;
            float s = 0.f;
            #pragma unroll
            for (int r = 0; r < 8; r++) s += sE[r][c];
            g_csp[(job * 8 + rb) * 64 + c] = s;
        }
    }

    gridbar(1);

    // ======== phase 3: chain (all 64 blocks; kind = aa1 | aa2) ========
    {
        float* E0s   = sm;
        float* E1s   = sm + 1 * 64 * ESTRIDE;
        float* E2s   = sm + 2 * 64 * ESTRIDE;
        float* buf0  = sm + 3 * 64 * ESTRIDE;
        float* buf1  = buf0 + 4 * BSTRIDE;
        float* sinvC = buf1 + 4 * BSTRIDE;   // [384]
        float* slloss = sinvC + 384;         // [4]
        int kind = bx >> 5;                 // 0: aa1, 1: aa2
        int b    = (bx >> 4) & 1;
        int r0   = (bx & 15) * 4;
        int j0   = b * 3;

        for (int i = tid; i < 384; i += 256) {
            int kk = i >> 6, idx = i & 63;
            float v;
            if (kk < 3) {
                v = __ldcg(&g_rs[(j0 + kk) * 64 + idx]);
            } else {
                int j = j0 + (kk - 3);
                v = 0.f;
                #pragma unroll
                for (int rb = 0; rb < 8; rb++) v += __ldcg(&g_csp[(j * 8 + rb) * 64 + idx]);
            }
            sinvC[i] = 1.0f / (v + 1e-5f);
        }
        int nmats = kind ? 3 : 2;
        for (int mat = 0; mat < nmats; mat++) {
            const float4* Eg = (const float4*)(g_E + (size_t)(j0 + mat) * 4096);
            float* Es = sm + mat * 64 * ESTRIDE;
            for (int i = tid; i < 1024; i += 256) {
                int n = i >> 4, mb = (i & 15) * 4;
                float4 v = __ldcg(Eg + i);
                Es[n * ESTRIDE + mb + 0] = v.x;
                Es[n * ESTRIDE + mb + 1] = v.y;
                Es[n * ESTRIDE + mb + 2] = v.z;
                Es[n * ESTRIDE + mb + 3] = v.w;
            }
        }
        __syncthreads();
        {
            int r = tid >> 6, m = tid & 63;
            buf0[r * BSTRIDE + m] = E0s[(r0 + r) * ESTRIDE + m]
                                    * sinvC[r0 + r] * sinvC[64 + m];
        }
        __syncthreads();

        float* res;
        if (kind == 0) {
            mm4v(buf0, E1s, false, sinvC + 256, buf1);  // P      -> *cinv1
            mm4v(buf1, E1s, true,  sinvC + 192, buf0);  // @A21_1 -> *cinv0
            mm4v(buf0, E0s, true,  nullptr,     buf1);  // @A21_0 = aa1
            res = buf1;
        } else {
            mm4v(buf0, E1s, false, sinvC + 128, buf1);  // P      -> *rinv2
            mm4v(buf1, E2s, false, sinvC + 320, buf0);  // @A12_2 -> *cinv2
            mm4v(buf0, E2s, true,  sinvC + 256, buf1);  // @A21_2 -> *cinv1
            mm4v(buf1, E1s, true,  sinvC + 192, buf0);  // @A21_1 -> *cinv0
            mm4v(buf0, E0s, true,  nullptr,     buf1);  // @A21_0 = aa2
            res = buf1;
        }

        {
            int r = tid >> 6, m = tid & 63;
            float* dst = out + aa_base + (size_t)(kind * B_ + b) * 4096;
            dst[(r0 + r) * 64 + m] = res[r * BSTRIDE + m];
            if (write_loss && tid < 4) {
                float s = 0.f;
                #pragma unroll 8
                for (int j = 0; j < 64; j++) s += res[tid * BSTRIDE + j];
                float diag = res[tid * BSTRIDE + (r0 + tid)] + 1e-20f;
                slloss[tid] = logf(s + 6.4e-19f) - logf(diag);
            }
            __syncthreads();
            if (write_loss && tid == 0) {
                float s = slloss[0] + slloss[1] + slloss[2] + slloss[3];
                atomicAdd(out, s * (1.0f / 128.0f));
            }
        }
    }
}

// ---------------- launch ----------------
extern "C" void kernel_launch(void* const* d_in, const int* in_sizes, int n_in,
                              void* d_out, int out_size) {
    const float* feats   = (const float*)d_in[0];
    const float* W_head  = (const float*)d_in[1];
    const int*   sp_mask = (const int*)  d_in[2];
    float* out = (float*)d_out;

    int aa_base    = (out_size > 2 * B_ * SP_ * SP_) ? 1 : 0;
    int write_loss = aa_base;

    cudaFuncSetAttribute(mega_kernel, cudaFuncAttributeMaxDynamicSharedMemorySize, SMEM_MEGA);

    fused_in_kernel<<<588, 256>>>(sp_mask, feats, W_head, out, write_loss);
    mega_kernel    <<<NBLK, 256, SMEM_MEGA>>>(out, aa_base, write_loss);
}